// round 9
// baseline (speedup 1.0000x reference)
#include <cuda_runtime.h>
#include <cuda_fp16.h>
#include <math.h>

// Problem constants
#define NB    8
#define C     528
#define CV4   (C/4)          // 132 groups of 4 channels
#define T     16
#define HH    32
#define WW    32
#define R     1024
#define OUTB  8
#define SR    2
#define SCALE (1.0f/16.0f)

#define MAXSUP 144           // max support pixels per roi (<= ~10x10)

// NHWC feature scratch in fp16: [b][y][x][c]
__device__ __half g_feat_h[NB * HH * WW * C];
// pooled scratch fp32: [roi][c]
__device__ float g_pooled[R * C];

// ---------------------------------------------------------------------------
// Kernel 1: temporal mean + NCHW -> NHWC transpose, fp32 accum, fp16 store
// ---------------------------------------------------------------------------
__global__ void mean_t_transpose_kernel(const float* __restrict__ x)
{
    __shared__ float tile[32][33];

    const int by = blockIdx.x;          // b*32 + y
    const int b  = by >> 5;
    const int y  = by & 31;
    const int cchunk = blockIdx.y;

    const int tx = threadIdx.x;
    const int ty = threadIdx.y;

    const int c = cchunk * 32 + ty;
    if (c < C) {
        const float* p = x + (((size_t)(b * C + c) * T) * HH + y) * WW + tx;
        float s0 = 0.f, s1 = 0.f;
        #pragma unroll
        for (int t = 0; t < T; t += 2) {
            s0 += __ldcs(p + (size_t)t       * (HH * WW));
            s1 += __ldcs(p + (size_t)(t + 1) * (HH * WW));
        }
        tile[ty][tx] = (s0 + s1) * (1.0f / T);
    }
    __syncthreads();

    const int c2 = cchunk * 32 + tx;
    if (c2 < C) {
        g_feat_h[(((size_t)(b * HH + y)) * WW + ty) * C + c2] =
            __float2half(tile[tx][ty]);
    }
}

// ---------------------------------------------------------------------------
// Kernel 2: ROI pooling with flattened support list.
// Phase A builds (offset, weight) list in smem; Phase B is a flat gather
// loop of fully independent loads (high MLP). grid: R, block: 160.
// ---------------------------------------------------------------------------
__global__ __launch_bounds__(160)
void roi_pool_kernel(const float* __restrict__ bbox)
{
    __shared__ float sAx[32];
    __shared__ float sAy[32];
    __shared__ int   sB;
    __shared__ int   sXlo, sNx, sYlo, sNy, sN;
    __shared__ int   sOff[MAXSUP];   // pixel offset (in uint2 units of CV4)
    __shared__ float sW[MAXSUP];

    const int tid = threadIdx.x;
    const int roi = blockIdx.x;

    // Phase A1: per-bin axis weights (warp0 = x, warp1 = y), deterministic
    if (tid < 64) {
        const int axis = tid >> 5;       // 0 = x, 1 = y
        const int bin  = tid & 31;
        const float* bb = bbox + roi * 5;
        if (tid == 0) sB = (int)bb[0];

        const float lo_c = bb[1 + axis] * SCALE - 0.5f;
        const float hi_c = bb[3 + axis] * SCALE - 0.5f;
        const float step = (hi_c - lo_c) * (1.0f / (OUTB * SR));

        float w = 0.f;
        #pragma unroll
        for (int s = 0; s < 16; s++) {
            const float v = lo_c + ((float)s + 0.5f) * step;
            const bool valid = (v >= -1.0f) && (v <= 32.0f);
            float vc   = fminf(fmaxf(v, 0.0f), 31.0f);
            float lof  = floorf(vc);
            float frac = vc - lof;
            int ilo = (int)lof;
            int ihi = min(ilo + 1, 31);
            if (valid) {
                if (ilo == bin) w += 1.0f - frac;
                if (ihi == bin) w += frac;
            }
        }
        if (axis) sAy[bin] = w; else sAx[bin] = w;

        unsigned m = __ballot_sync(0xFFFFFFFF, w != 0.f);
        if (bin == 0) {
            int lo, n;
            if (m == 0u) { lo = 0; n = 0; }
            else { lo = __ffs(m) - 1; n = (31 - __clz(m)) - lo + 1; }
            if (axis) { sYlo = lo; sNy = n; }
            else      { sXlo = lo; sNx = n; }
        }
    }
    __syncthreads();

    // Phase A2: flatten support into (offset, weight) list
    {
        const int nx = sNx, ny = sNy;
        const int n  = nx * ny;
        if (tid == 0) sN = n;
        for (int i = tid; i < n; i += 160) {
            const int iy = i / nx;
            const int ix = i - iy * nx;
            const int y  = sYlo + iy;
            const int xp = sXlo + ix;
            sOff[i] = (y * WW + xp) * CV4;
            sW[i]   = sAy[y] * sAx[xp] * (1.0f / 256.0f);
        }
    }
    __syncthreads();

    // Phase B: flat gather, all loads independent
    if (tid < CV4) {
        const int n = sN;
        const uint2* base = (const uint2*)g_feat_h
                          + (size_t)sB * (HH * WW * CV4) + tid;

        float4 acc = make_float4(0.f, 0.f, 0.f, 0.f);
        #pragma unroll 4
        for (int i = 0; i < n; i++) {
            const float w   = sW[i];
            const uint2 raw = base[sOff[i]];
            const float2 f01 = __half22float2(*(const __half2*)&raw.x);
            const float2 f23 = __half22float2(*(const __half2*)&raw.y);
            acc.x = fmaf(w, f01.x, acc.x);
            acc.y = fmaf(w, f01.y, acc.y);
            acc.z = fmaf(w, f23.x, acc.z);
            acc.w = fmaf(w, f23.y, acc.w);
        }
        ((float4*)g_pooled)[(size_t)roi * CV4 + tid] = acc;
    }
}

// ---------------------------------------------------------------------------
// Kernel 3: MLP 528 -> 128 (relu) -> 32 -> 1 (sigmoid), 8 rois per block.
// grid: R/8 = 128, block: 256. Layer 1 register-tiled GEMM.
// ---------------------------------------------------------------------------
#define MR 8

__global__ __launch_bounds__(256)
void mlp_kernel(const float* __restrict__ W1, const float* __restrict__ b1,
                const float* __restrict__ W2, const float* __restrict__ b2,
                const float* __restrict__ W3, const float* __restrict__ b3,
                float* __restrict__ out)
{
    __shared__ float sPooled[MR][C];
    __shared__ float sH1[MR][128];
    __shared__ float sH2[MR][32];

    const int tid  = threadIdx.x;
    const int roi0 = blockIdx.x * MR;

    {
        const float4* gp4 = (const float4*)g_pooled + (size_t)roi0 * CV4;
        float4* sp4 = (float4*)&sPooled[0][0];
        #pragma unroll
        for (int u = tid; u < MR * CV4; u += 256)
            sp4[u] = gp4[u];
    }
    __syncthreads();

    // Layer 1
    {
        const int lane = tid & 31;
        const int w    = tid >> 5;            // warp 0..7
        const int part = lane >> 2;           // 0..7 (c-part, 66 each)
        const int jq   = lane & 3;
        const int j4   = w * 4 + jq;          // float4 index over j (0..31)
        const int c0   = part * 66;

        const float4* W1_4 = (const float4*)W1;   // [c][32]

        float4 a[MR];
        #pragma unroll
        for (int r = 0; r < MR; r++) a[r] = make_float4(0.f, 0.f, 0.f, 0.f);

        #pragma unroll 2
        for (int c = c0; c < c0 + 66; c++) {
            const float4 wv = W1_4[c * 32 + j4];
            #pragma unroll
            for (int r = 0; r < MR; r++) {
                const float p = sPooled[r][c];
                a[r].x = fmaf(p, wv.x, a[r].x);
                a[r].y = fmaf(p, wv.y, a[r].y);
                a[r].z = fmaf(p, wv.z, a[r].z);
                a[r].w = fmaf(p, wv.w, a[r].w);
            }
        }

        #pragma unroll
        for (int off = 4; off <= 16; off <<= 1) {
            #pragma unroll
            for (int r = 0; r < MR; r++) {
                a[r].x += __shfl_xor_sync(0xFFFFFFFF, a[r].x, off);
                a[r].y += __shfl_xor_sync(0xFFFFFFFF, a[r].y, off);
                a[r].z += __shfl_xor_sync(0xFFFFFFFF, a[r].z, off);
                a[r].w += __shfl_xor_sync(0xFFFFFFFF, a[r].w, off);
            }
        }

        if (part == 0) {
            const float4 bb = ((const float4*)b1)[j4];
            #pragma unroll
            for (int r = 0; r < MR; r++) {
                float4 h;
                h.x = fmaxf(a[r].x + bb.x, 0.f);
                h.y = fmaxf(a[r].y + bb.y, 0.f);
                h.z = fmaxf(a[r].z + bb.z, 0.f);
                h.w = fmaxf(a[r].w + bb.w, 0.f);
                ((float4*)&sH1[r][0])[j4] = h;
            }
        }
    }
    __syncthreads();

    // Layer 2
    {
        const int r = tid >> 5;
        const int j = tid & 31;
        const float* h = sH1[r];
        float a0 = 0.f, a1 = 0.f;
        #pragma unroll
        for (int k = 0; k < 128; k += 2) {
            a0 = fmaf(h[k],     W2[(k)     * 32 + j], a0);
            a1 = fmaf(h[k + 1], W2[(k + 1) * 32 + j], a1);
        }
        sH2[r][j] = a0 + a1 + b2[j];
    }
    __syncthreads();

    // Layer 3 + sigmoid
    {
        const int r    = tid >> 5;
        const int lane = tid & 31;
        float v = sH2[r][lane] * W3[lane];
        #pragma unroll
        for (int off = 16; off > 0; off >>= 1)
            v += __shfl_xor_sync(0xFFFFFFFF, v, off);
        if (lane == 0)
            out[roi0 + r] = 1.0f / (1.0f + expf(-(v + b3[0])));
    }
}

// ---------------------------------------------------------------------------
extern "C" void kernel_launch(void* const* d_in, const int* in_sizes, int n_in,
                              void* d_out, int out_size)
{
    const float* x    = (const float*)d_in[0];
    const float* bbox = (const float*)d_in[1];
    const float* W1   = (const float*)d_in[2];
    const float* b1   = (const float*)d_in[3];
    const float* W2   = (const float*)d_in[4];
    const float* b2   = (const float*)d_in[5];
    const float* W3   = (const float*)d_in[6];
    const float* b3   = (const float*)d_in[7];
    float* out = (float*)d_out;

    dim3 g1(NB * HH, (C + 31) / 32);
    dim3 t1(32, 32);
    mean_t_transpose_kernel<<<g1, t1>>>(x);

    roi_pool_kernel<<<R, 160>>>(bbox);

    mlp_kernel<<<R / MR, 256>>>(W1, b1, W2, b2, W3, b3, out);
}